// round 2
// baseline (speedup 1.0000x reference)
#include <cuda_runtime.h>
#include <cuda_bf16.h>
#include <cstdint>

// Problem dims
#define NXR 8192
#define NYR 8192
#define DK  512

// Tile config
#define TM 128
#define TN 128
#define TK 32
#define KSTEPS (DK / TK)          // 16
#define STAGES 3

// SMEM layout: per stage, A tile then B tile. Rows padded to 40 b16 (80B) for
// conflict-free ldmatrix (bank starts 0,20,8,28,16,4,24,12 - all distinct).
#define ASTRIDE_B16 40
#define TILE_BYTES  (128 * ASTRIDE_B16 * 2)      // 10240
#define STAGE_BYTES (2 * TILE_BYTES)             // 20480
#define SMEM_TOTAL  (STAGES * STAGE_BYTES)       // 61440

// bf16 scratch + row norms (device globals: no allocation allowed)
__device__ __nv_bfloat16 g_Xb[(size_t)NXR * DK];
__device__ __nv_bfloat16 g_Yb[(size_t)NYR * DK];
__device__ float g_x2[NXR];
__device__ float g_y2[NYR];

// ---------------- PTX helpers ----------------
__device__ __forceinline__ uint32_t smem_u32(const void* p) {
    uint32_t a;
    asm("{ .reg .u64 t; cvta.to.shared.u64 t, %1; cvt.u32.u64 %0, t; }" : "=r"(a) : "l"(p));
    return a;
}

#define CP_ASYNC16(saddr, gptr) \
    asm volatile("cp.async.cg.shared.global [%0], [%1], 16;" \
                 :: "r"(saddr), "l"(gptr) : "memory")

#define CP_COMMIT() asm volatile("cp.async.commit_group;" ::: "memory")
#define CP_WAIT(n)  asm volatile("cp.async.wait_group %0;" :: "n"(n) : "memory")

#define LDSM_X4(r, addr) \
    asm volatile("ldmatrix.sync.aligned.m8n8.x4.shared.b16 {%0,%1,%2,%3}, [%4];" \
                 : "=r"((r)[0]), "=r"((r)[1]), "=r"((r)[2]), "=r"((r)[3]) : "r"(addr))

#define MMA16816(d, a, b0, b1) \
    asm volatile("mma.sync.aligned.m16n8k16.row.col.f32.bf16.bf16.f32 " \
                 "{%0,%1,%2,%3}, {%4,%5,%6,%7}, {%8,%9}, {%0,%1,%2,%3};" \
                 : "+f"((d)[0]), "+f"((d)[1]), "+f"((d)[2]), "+f"((d)[3]) \
                 : "r"((a)[0]), "r"((a)[1]), "r"((a)[2]), "r"((a)[3]), \
                   "r"(b0), "r"(b1))

// ---------------- Prepass: f32 -> bf16 + row squared norms ----------------
__global__ void __launch_bounds__(128) rbf_prep_kernel(
    const float* __restrict__ x, const float* __restrict__ y) {
    __shared__ float red[4];
    int b = blockIdx.x;
    int t = threadIdx.x;
    const float* src;
    __nv_bfloat16* dst;
    float* nrm;
    int row;
    if (b < NXR) { row = b;       src = x + (size_t)row * DK; dst = g_Xb + (size_t)row * DK; nrm = g_x2; }
    else         { row = b - NXR; src = y + (size_t)row * DK; dst = g_Yb + (size_t)row * DK; nrm = g_y2; }

    float4 v = reinterpret_cast<const float4*>(src)[t];          // 128 threads x 4 = 512
    float s = v.x * v.x + v.y * v.y + v.z * v.z + v.w * v.w;
    __nv_bfloat162 h0 = __floats2bfloat162_rn(v.x, v.y);
    __nv_bfloat162 h1 = __floats2bfloat162_rn(v.z, v.w);
    reinterpret_cast<__nv_bfloat162*>(dst)[t * 2 + 0] = h0;
    reinterpret_cast<__nv_bfloat162*>(dst)[t * 2 + 1] = h1;

    #pragma unroll
    for (int o = 16; o; o >>= 1) s += __shfl_xor_sync(0xffffffffu, s, o);
    if ((t & 31) == 0) red[t >> 5] = s;
    __syncthreads();
    if (t == 0) nrm[row] = red[0] + red[1] + red[2] + red[3];
}

// ---------------- Tile loader (cp.async) ----------------
__device__ __forceinline__ void load_tile(
    uint32_t stage_base, const __nv_bfloat16* __restrict__ Arows,
    const __nv_bfloat16* __restrict__ Brows, int kstep, int tid) {
    #pragma unroll
    for (int h = 0; h < 2; h++) {
        int idx = tid + h * 256;        // 0..511
        int row = idx >> 2;
        int seg = idx & 3;
        uint32_t soff = (uint32_t)(row * (ASTRIDE_B16 * 2) + seg * 16);
        const __nv_bfloat16* ga = Arows + (size_t)row * DK + kstep * TK + seg * 8;
        CP_ASYNC16(stage_base + soff, ga);
        const __nv_bfloat16* gb = Brows + (size_t)row * DK + kstep * TK + seg * 8;
        CP_ASYNC16(stage_base + TILE_BYTES + soff, gb);
    }
}

// ---------------- Main kernel: mma.sync GEMM + RBF epilogue ----------------
__global__ void __launch_bounds__(256, 1) rbf_gemm_kernel(
    float* __restrict__ out, const float* __restrict__ gamma_p) {
    extern __shared__ char smem[];
    const uint32_t sb = smem_u32(smem);
    const int tid = threadIdx.x;
    const int wid = tid >> 5;
    const int lid = tid & 31;
    const int wm = wid & 3;            // warp row: 32-row slab
    const int wn = wid >> 2;           // warp col: 64-col slab
    const int mbase = blockIdx.y * TM;
    const int nbase = blockIdx.x * TN;

    const __nv_bfloat16* Arows = g_Xb + (size_t)mbase * DK;
    const __nv_bfloat16* Brows = g_Yb + (size_t)nbase * DK;

    // Prefetch first STAGES-1 stages
    #pragma unroll
    for (int s = 0; s < STAGES - 1; s++) {
        load_tile(sb + s * STAGE_BYTES, Arows, Brows, s, tid);
        CP_COMMIT();
    }

    float acc[2][8][4];
    #pragma unroll
    for (int i = 0; i < 2; i++)
        #pragma unroll
        for (int j = 0; j < 8; j++)
            #pragma unroll
            for (int q = 0; q < 4; q++) acc[i][j][q] = 0.0f;

    const int lrow = lid & 15;         // ldmatrix row within 16
    const int lhalf = lid >> 4;        // k-half selector

    for (int k = 0; k < KSTEPS; k++) {
        CP_WAIT(STAGES - 2);
        __syncthreads();
        const uint32_t st = sb + (k % STAGES) * STAGE_BYTES;

        // A fragments: 2 m16 tiles x 2 k16 halves
        uint32_t a[2][2][4];
        #pragma unroll
        for (int tm = 0; tm < 2; tm++)
            #pragma unroll
            for (int kk = 0; kk < 2; kk++) {
                uint32_t addr = st + (uint32_t)((wm * 32 + tm * 16 + lrow) * 80
                                                + kk * 32 + lhalf * 16);
                LDSM_X4(a[tm][kk], addr);
            }

        // B fragments: 4 n16 pairs x 2 k16 halves  (B stored [n][k], row.col mma)
        uint32_t bfr[4][2][4];
        #pragma unroll
        for (int p = 0; p < 4; p++)
            #pragma unroll
            for (int kk = 0; kk < 2; kk++) {
                uint32_t addr = st + TILE_BYTES
                              + (uint32_t)((wn * 64 + p * 16 + lrow) * 80
                                           + kk * 32 + lhalf * 16);
                LDSM_X4(bfr[p][kk], addr);
            }

        // 32 MMAs: regs r0=(n0-7), r1=(n8-15) for k0-7; r2, r3 for k8-15
        #pragma unroll
        for (int tm = 0; tm < 2; tm++)
            #pragma unroll
            for (int p = 0; p < 4; p++)
                #pragma unroll
                for (int kk = 0; kk < 2; kk++) {
                    MMA16816(acc[tm][2 * p + 0], a[tm][kk], bfr[p][kk][0], bfr[p][kk][2]);
                    MMA16816(acc[tm][2 * p + 1], a[tm][kk], bfr[p][kk][1], bfr[p][kk][3]);
                }

        if (k + STAGES - 1 < KSTEPS) {
            load_tile(sb + ((k + STAGES - 1) % STAGES) * STAGE_BYTES,
                      Arows, Brows, k + STAGES - 1, tid);
        }
        CP_COMMIT();
    }

    // ---------------- Epilogue: sq = x2 + y2 - 2*dot; out = exp(-gamma*sq) ----------------
    const float gam = __ldg(gamma_p);
    #pragma unroll
    for (int tm = 0; tm < 2; tm++) {
        const int m0 = mbase + wm * 32 + tm * 16 + (lid >> 2);
        const float x2a = g_x2[m0];
        const float x2b = g_x2[m0 + 8];
        #pragma unroll
        for (int nn = 0; nn < 8; nn++) {
            const int n0 = nbase + wn * 64 + nn * 8 + (lid & 3) * 2;
            const float y2a = g_y2[n0];
            const float y2b = g_y2[n0 + 1];
            const float* c = acc[tm][nn];
            float2 v0, v1;
            v0.x = __expf(-gam * fmaxf(x2a + y2a - 2.0f * c[0], 0.0f));
            v0.y = __expf(-gam * fmaxf(x2a + y2b - 2.0f * c[1], 0.0f));
            v1.x = __expf(-gam * fmaxf(x2b + y2a - 2.0f * c[2], 0.0f));
            v1.y = __expf(-gam * fmaxf(x2b + y2b - 2.0f * c[3], 0.0f));
            *reinterpret_cast<float2*>(out + (size_t)m0 * NYR + n0) = v0;
            *reinterpret_cast<float2*>(out + (size_t)(m0 + 8) * NYR + n0) = v1;
        }
    }
}

extern "C" void kernel_launch(void* const* d_in, const int* in_sizes, int n_in,
                              void* d_out, int out_size) {
    const float* x = (const float*)d_in[0];
    const float* y = (const float*)d_in[1];
    const float* gamma = (const float*)d_in[2];
    float* out = (float*)d_out;

    rbf_prep_kernel<<<NXR + NYR, 128>>>(x, y);

    cudaFuncSetAttribute(rbf_gemm_kernel,
                         cudaFuncAttributeMaxDynamicSharedMemorySize, SMEM_TOTAL);
    dim3 grid(NYR / TN, NXR / TM);
    rbf_gemm_kernel<<<grid, 256, SMEM_TOTAL>>>(out, gamma);
}